// round 14
// baseline (speedup 1.0000x reference)
#include <cuda_runtime.h>
#include <cuda_fp16.h>
#include <cstdint>

// ---------------- problem constants ----------------
#define BATCH 32
#define CIN   512
#define COUT  512
#define QL    4096
#define LPAD  4098          // 1 zero row of padding at each end (conv pad=1)

// GEMM tiling: persistent, CTA tile 128(M) x 256(N), 16 warps of 32x64, 1 CTA/SM
#define TILE_M 128
#define TILE_N 256
#define CPT 8               // c-chunks per tile; each chunk covers ALL 3 taps
#define A_TAP_BYTES 16384
#define B_OFF 49152
#define STAGE_BYTES 82176
#define SCRATCH_OFF (2 * STAGE_BYTES)            // 164352: quant transpose scratch
#define SCRATCH_BYTES (128 * 66 * 2)             // 16896
#define FLAG_OFF (SCRATCH_OFF + SCRATCH_BYTES)   // 181248
#define SMEM_DYN (FLAG_OFF + 16)                 // 181264 B

#define GRID_P 148
#define NTILES ((QL / TILE_N) * (COUT / TILE_M) * BATCH)   // 2048
#define NQJOBS (BATCH * 256)                     // 8192 quant jobs (64l x 128c each)

// ---------------- device scratch ----------------
__device__ __align__(16) __half g_qx[(size_t)BATCH * LPAD * CIN];   // [b][l+1][c] quantized x
__device__ __align__(16) __half g_w2[(size_t)3 * COUT * CIN];       // [k][o][c]  w'' = qw*sw*sa
__device__ int g_qcnt[BATCH * 16];               // region counters (b, l/256); target 16

// ---------------- base-ISA helpers ----------------
__device__ __forceinline__ uint32_t smem_u32(const void* p) {
    uint32_t a;
    asm("{ .reg .u64 t; cvta.to.shared.u64 t, %1; cvt.u32.u64 %0, t; }" : "=r"(a) : "l"(p));
    return a;
}
#define SWU(u, r) (((u) ^ ((r) & 7)) << 4)

__device__ __forceinline__ void cp_async16(uint32_t saddr, const void* gptr) {
    asm volatile("cp.async.cg.shared.global [%0], [%1], 16;" :: "r"(saddr), "l"(gptr));
}
#define CP_COMMIT() asm volatile("cp.async.commit_group;" ::: "memory")
#define CP_WAIT(n)  asm volatile("cp.async.wait_group %0;" :: "n"(n) : "memory")

__device__ __forceinline__ void ldm_x4(uint32_t& r0, uint32_t& r1, uint32_t& r2, uint32_t& r3, uint32_t a) {
    asm volatile("ldmatrix.sync.aligned.m8n8.x4.shared.b16 {%0,%1,%2,%3}, [%4];"
                 : "=r"(r0), "=r"(r1), "=r"(r2), "=r"(r3) : "r"(a));
}
__device__ __forceinline__ void mma16816(float& c0, float& c1, float& c2, float& c3,
                                         uint32_t a0, uint32_t a1, uint32_t a2, uint32_t a3,
                                         uint32_t b0, uint32_t b1) {
    asm("mma.sync.aligned.m16n8k16.row.col.f32.f16.f16.f32 "
        "{%0,%1,%2,%3}, {%4,%5,%6,%7}, {%8,%9}, {%0,%1,%2,%3};"
        : "+f"(c0), "+f"(c1), "+f"(c2), "+f"(c3)
        : "r"(a0), "r"(a1), "r"(a2), "r"(a3), "r"(b0), "r"(b1));
}

// ---------------- kernel 1: weight prep + counter reset ----------------
__global__ void prep_w_kernel(const float* __restrict__ w,
                              const float* __restrict__ a_scale,
                              const float* __restrict__ w_scale) {
    int o = blockIdx.x, c = threadIdx.x;
    if (blockIdx.x == 0) g_qcnt[c % (BATCH * 16)] = 0;   // c covers 0..511 = all counters
    float sw = fabsf(w_scale[o]) + 1e-8f;
    float sa = fabsf(a_scale[c]) + 1e-8f;
#pragma unroll
    for (int k = 0; k < 3; k++) {
        float v = w[((size_t)o * CIN + c) * 3 + k];
        float q = fminf(fmaxf(rintf(v / sw), -128.f), 127.f);
        float wpp = (q * sw) * sa;
        g_w2[((size_t)k * COUT + o) * CIN + c] = __float2half_rn(wpp);
    }
}

// ---------------- kernel 2: fused persistent quant + GEMM-conv ----------------
__global__ void __launch_bounds__(512, 1)
qconv_gemm(const float* __restrict__ bias, float* __restrict__ out,
           const float* __restrict__ x, const float* __restrict__ a_scale) {
    extern __shared__ __align__(16) char smem[];
    const uint32_t sbase = smem_u32(smem);
    const int tid  = threadIdx.x;
    const int wid  = tid >> 5;      // 0..15
    const int lane = tid & 31;
    const int bid  = blockIdx.x;

    const int wm = (wid & 3) * 32;
    const int wn = (wid >> 2) * 64;

    const uint4* gw = reinterpret_cast<const uint4*>(g_w2);
    const uint4* gx = reinterpret_cast<const uint4*>(g_qx);
    volatile int* flag = reinterpret_cast<volatile int*>(smem + FLAG_OFF);

    const int ntiles = (NTILES - 1 - bid) / GRID_P + 1;

    // ---- quant job: 64 l x 128 c, conflict-free transpose via permuted rows ----
    __half (*qt)[66] = reinterpret_cast<__half(*)[66]>(smem + SCRATCH_OFF);
    auto quant_job = [&](int q) {
        const int b   = q >> 8;
        const int rem = q & 255;
        const int l0  = (rem >> 2) * 64;
        const int c0  = (rem & 3) * 128;
        if (l0 == 0 && tid < 32)
            *reinterpret_cast<uint2*>(&g_qx[((size_t)b * LPAD) * CIN + c0 + tid * 4]) = make_uint2(0u, 0u);
        if (l0 == QL - 64 && tid < 32)
            *reinterpret_cast<uint2*>(&g_qx[((size_t)b * LPAD + LPAD - 1) * CIN + c0 + tid * 4]) = make_uint2(0u, 0u);
#pragma unroll
        for (int jj = 0; jj < 8; jj++) {
            int ci = jj * 16 + wid;
            int row = (ci & 3) * 32 + (ci >> 2);
            float s = fabsf(a_scale[c0 + ci]) + 1e-8f;
            float2 v = *reinterpret_cast<const float2*>(
                &x[((size_t)b * CIN + c0 + ci) * QL + l0 + lane * 2]);
            float q0 = fminf(fmaxf(rintf(v.x / s), -128.f), 127.f);
            float q1 = fminf(fmaxf(rintf(v.y / s), -128.f), 127.f);
            *reinterpret_cast<half2*>(&qt[row][lane * 2]) = __floats2half2_rn(q0, q1);
        }
        __syncthreads();
#pragma unroll
        for (int it = 0; it < 4; it++) {
            int l = it * 16 + wid;
            half2 p0 = __halves2half2(qt[lane +  0][l], qt[lane + 32][l]);
            half2 p1 = __halves2half2(qt[lane + 64][l], qt[lane + 96][l]);
            uint2 w;
            w.x = *reinterpret_cast<uint32_t*>(&p0);
            w.y = *reinterpret_cast<uint32_t*>(&p1);
            *reinterpret_cast<uint2*>(
                &g_qx[((size_t)b * LPAD + l0 + l + 1) * CIN + c0 + lane * 4]) = w;
        }
        __threadfence();
        __syncthreads();
        if (tid == 0) atomicAdd(&g_qcnt[b * 16 + (l0 >> 8)], 1);
    };

    int nextq = bid;
    auto do_quota = [&](int blimit) {
        while (nextq < NQJOBS && (nextq >> 8) < blimit) { quant_job(nextq); nextq += GRID_P; }
    };

    // ---- tile chunk loader ----
    auto load_chunk = [&](int t, int cc) {
        const int b  = t >> 6;
        const int o0 = ((t >> 4) & 3) * TILE_M;
        const int L0 = (t & 15) * TILE_N;
        const uint32_t sb = sbase + (uint32_t)(cc & 1) * STAGE_BYTES;
#pragma unroll
        for (int k = 0; k < 3; k++)
#pragma unroll
            for (int j2 = 0; j2 < 2; j2++) {
                int e = tid + j2 * 512;
                int r = e >> 3, u = e & 7;
                cp_async16(sb + k * A_TAP_BYTES + (uint32_t)(r * 128) + SWU(u, r),
                           &gw[(size_t)(k * COUT + o0 + r) * 64 + cc * 8 + u]);
            }
#pragma unroll
        for (int j2 = 0; j2 < 5; j2++) {
            int e = tid + j2 * 512;
            if (e < 2064) {
                int r = e >> 3, u = e & 7;
                cp_async16(sb + B_OFF + (uint32_t)(r * 128) + SWU(u, r),
                           &gx[((size_t)b * LPAD + L0 + r) * 64 + cc * 8 + u]);
            }
        }
    };

    float acc[2][8][4];
    const int lrow = (lane & 7) + ((lane >> 3) & 1) * 8;
    const int lcol = (lane >> 4);

    auto compute_tap = [&](uint32_t sb, int tap) {
#pragma unroll
        for (int ks = 0; ks < 4; ks++) {
            const int u = ks * 2 + lcol;
            uint32_t bf[4][4];
#pragma unroll
            for (int t = 0; t < 4; t++) {
                int r = wn + t * 16 + lrow + tap;
                ldm_x4(bf[t][0], bf[t][1], bf[t][2], bf[t][3],
                       sb + B_OFF + r * 128 + SWU(u, r));
            }
            uint32_t af[2][4];
#pragma unroll
            for (int t = 0; t < 2; t++) {
                int r = wm + t * 16 + lrow;
                ldm_x4(af[t][0], af[t][1], af[t][2], af[t][3],
                       sb + tap * A_TAP_BYTES + r * 128 + SWU(u, r));
            }
#pragma unroll
            for (int mi = 0; mi < 2; mi++)
#pragma unroll
                for (int t = 0; t < 4; t++) {
                    mma16816(acc[mi][t*2  ][0], acc[mi][t*2  ][1], acc[mi][t*2  ][2], acc[mi][t*2  ][3],
                             af[mi][0], af[mi][1], af[mi][2], af[mi][3], bf[t][0], bf[t][2]);
                    mma16816(acc[mi][t*2+1][0], acc[mi][t*2+1][1], acc[mi][t*2+1][2], acc[mi][t*2+1][3],
                             af[mi][0], af[mi][1], af[mi][2], af[mi][3], bf[t][1], bf[t][3]);
                }
        }
    };

    bool prefetched = false;

    for (int step = 0; step < ntiles; step++) {
        const int t  = bid + step * GRID_P;
        const int b  = t >> 6;
        const int o0 = ((t >> 4) & 3) * TILE_M;
        const int L0 = (t & 15) * TILE_N;
        const int r  = L0 >> 8;

        // invariant: own quant jobs for batches < b+3 done before this tile
        do_quota(b + 3);

        if (!prefetched) {
            if (tid == 0) {
                volatile int* c = g_qcnt;
                int i0 = b * 16 + (r > 0 ? r - 1 : 0);
                int i1 = b * 16 + r;
                int i2 = b * 16 + (r < 15 ? r + 1 : 15);
                while (c[i0] < 16) {}
                while (c[i1] < 16) {}
                while (c[i2] < 16) {}
            }
            __syncthreads();
            load_chunk(t, 0); CP_COMMIT();
        }
        prefetched = false;

#pragma unroll
        for (int mi = 0; mi < 2; mi++)
#pragma unroll
            for (int nj = 0; nj < 8; nj++)
#pragma unroll
                for (int q = 0; q < 4; q++) acc[mi][nj][q] = 0.f;

        for (int cc = 0; cc < 8; cc++) {
            CP_WAIT(0);                   // this thread's group (chunk cc) complete
            if (cc == 7 && tid == 0) {    // next-tile readiness check, pre-barrier
                int ok = 0;
                if (step + 1 < ntiles) {
                    int tn = t + GRID_P;
                    int bn = tn >> 6;
                    int rn = ((tn & 15) * TILE_N) >> 8;
                    volatile int* c = g_qcnt;
                    int i0 = bn * 16 + (rn > 0 ? rn - 1 : 0);
                    int i1 = bn * 16 + rn;
                    int i2 = bn * 16 + (rn < 15 ? rn + 1 : 15);
                    ok = (c[i0] >= 16) && (c[i1] >= 16) && (c[i2] >= 16);
                }
                *flag = ok;
            }
            __syncthreads();              // stage cc&1 visible; compute(cc-1) done; flag uniform

            const uint32_t sb = sbase + (uint32_t)(cc & 1) * STAGE_BYTES;
            compute_tap(sb, 0);
            if (cc < 7) { load_chunk(t, cc + 1); CP_COMMIT(); }
            else if (*flag) { load_chunk(t + GRID_P, 0); CP_COMMIT(); prefetched = true; }
            compute_tap(sb, 1);
            compute_tap(sb, 2);
        }

        // ---- register-only epilogue (overlaps prefetched loads) ----
#pragma unroll
        for (int mi = 0; mi < 2; mi++) {
            int r0 = wm + mi * 16 + (lane >> 2);
            int o_a = o0 + r0, o_b = o0 + r0 + 8;
            float bv0 = bias[o_a], bv1 = bias[o_b];
            float* pa = out + ((size_t)b * COUT + o_a) * QL + L0;
            float* pb = out + ((size_t)b * COUT + o_b) * QL + L0;
#pragma unroll
            for (int nj = 0; nj < 8; nj++) {
                int col = wn + nj * 8 + (lane & 3) * 2;
                float2 v0 = make_float2(acc[mi][nj][0] + bv0, acc[mi][nj][1] + bv0);
                float2 v1 = make_float2(acc[mi][nj][2] + bv1, acc[mi][nj][3] + bv1);
                *reinterpret_cast<float2*>(pa + col) = v0;
                *reinterpret_cast<float2*>(pb + col) = v1;
            }
        }
    }

    do_quota(BATCH);   // safety drain of any remaining own quant jobs
}

// ---------------- launch ----------------
extern "C" void kernel_launch(void* const* d_in, const int* in_sizes, int n_in,
                              void* d_out, int out_size) {
    (void)in_sizes; (void)n_in; (void)out_size;
    const float* x       = (const float*)d_in[0];
    const float* weight  = (const float*)d_in[1];
    const float* bias    = (const float*)d_in[2];
    const float* a_scale = (const float*)d_in[3];
    const float* w_scale = (const float*)d_in[4];
    float* out = (float*)d_out;

    prep_w_kernel<<<COUT, CIN>>>(weight, a_scale, w_scale);

    cudaFuncSetAttribute(qconv_gemm, cudaFuncAttributeMaxDynamicSharedMemorySize, SMEM_DYN);
    qconv_gemm<<<GRID_P, 512, SMEM_DYN>>>(bias, out, x, a_scale);
}

// round 15
// speedup vs baseline: 1.4129x; 1.4129x over previous
#include <cuda_runtime.h>
#include <cuda_fp16.h>
#include <cstdint>

// ---------------- problem constants ----------------
#define BATCH 32
#define CIN   512
#define COUT  512
#define QL    4096
#define LPAD  4098          // 1 zero row of padding at each end (conv pad=1)

// GEMM tiling: persistent, CTA tile 128(M) x 256(N), 16 warps of 32x64, 1 CTA/SM
#define TILE_M 128
#define TILE_N 256
#define TILE_K 64           // c per chunk (128B fp16 rows, swizzled)
#define CPT 8               // c-chunks per tile; each chunk covers ALL 3 taps
#define NSTAGE 2
// stage: A = 3 taps * 128 rows * 128B = 49152 ; B = 258 rows * 128B = 33024
#define A_TAP_BYTES 16384
#define B_OFF 49152
#define STAGE_BYTES 82176
#define SMEM_DYN (NSTAGE * STAGE_BYTES)   // 164352 B

#define GRID_P 148
#define NTILES ((QL / TILE_N) * (COUT / TILE_M) * BATCH)   // 16*4*32 = 2048

// ---------------- device scratch ----------------
__device__ __align__(16) __half g_qx[(size_t)BATCH * LPAD * CIN];   // [b][l+1][c] quantized x (exact ints)
__device__ __align__(16) __half g_w2[(size_t)3 * COUT * CIN];       // [k][o][c]  w'' = qw*sw*sa (fp16)

// ---------------- base-ISA helpers ----------------
__device__ __forceinline__ uint32_t smem_u32(const void* p) {
    uint32_t a;
    asm("{ .reg .u64 t; cvta.to.shared.u64 t, %1; cvt.u32.u64 %0, t; }" : "=r"(a) : "l"(p));
    return a;
}
#define SWU(u, r) (((u) ^ ((r) & 7)) << 4)   // 16B-unit swizzle within a 128B row

__device__ __forceinline__ void cp_async16(uint32_t saddr, const void* gptr) {
    asm volatile("cp.async.cg.shared.global [%0], [%1], 16;" :: "r"(saddr), "l"(gptr));
}
#define CP_COMMIT() asm volatile("cp.async.commit_group;" ::: "memory")
#define CP_WAIT(n)  asm volatile("cp.async.wait_group %0;" :: "n"(n) : "memory")

__device__ __forceinline__ void ldm_x4(uint32_t& r0, uint32_t& r1, uint32_t& r2, uint32_t& r3, uint32_t a) {
    asm volatile("ldmatrix.sync.aligned.m8n8.x4.shared.b16 {%0,%1,%2,%3}, [%4];"
                 : "=r"(r0), "=r"(r1), "=r"(r2), "=r"(r3) : "r"(a));
}
__device__ __forceinline__ void mma16816(float& c0, float& c1, float& c2, float& c3,
                                         uint32_t a0, uint32_t a1, uint32_t a2, uint32_t a3,
                                         uint32_t b0, uint32_t b1) {
    asm("mma.sync.aligned.m16n8k16.row.col.f32.f16.f16.f32 "
        "{%0,%1,%2,%3}, {%4,%5,%6,%7}, {%8,%9}, {%0,%1,%2,%3};"
        : "+f"(c0), "+f"(c1), "+f"(c2), "+f"(c3)
        : "r"(a0), "r"(a1), "r"(a2), "r"(a3), "r"(b0), "r"(b1));
}

// ---------------- kernel 1: weight prep ----------------
// w'' = clip(rint(w/sw))*sw*sa, fp16; layout [k][o][c]
__global__ void prep_w_kernel(const float* __restrict__ w,
                              const float* __restrict__ a_scale,
                              const float* __restrict__ w_scale) {
    int o = blockIdx.x, c = threadIdx.x;
    float sw = fabsf(w_scale[o]) + 1e-8f;
    float sa = fabsf(a_scale[c]) + 1e-8f;
#pragma unroll
    for (int k = 0; k < 3; k++) {
        float v = w[((size_t)o * CIN + c) * 3 + k];
        float q = fminf(fmaxf(rintf(v / sw), -128.f), 127.f);
        float wpp = (q * sw) * sa;
        g_w2[((size_t)k * COUT + o) * CIN + c] = __float2half_rn(wpp);
    }
}

// ---------------- kernel 2: quantize + transpose x (conflict-free, pad fused) ----------------
__global__ void __launch_bounds__(256)
quant_kernel(const float* __restrict__ x, const float* __restrict__ a_scale) {
    __shared__ __half tile[128][66];
    const int tid  = threadIdx.x;
    const int warp = tid >> 5;
    const int lane = tid & 31;
    const int l0 = blockIdx.x * 64;
    const int c0 = blockIdx.y * 128;
    const int b  = blockIdx.z;

    if (blockIdx.x == 0 && tid < 32) {
        *reinterpret_cast<uint2*>(&g_qx[((size_t)b * LPAD + 0) * CIN + c0 + tid * 4]) =
            make_uint2(0u, 0u);
    }
    if (blockIdx.x == gridDim.x - 1 && tid < 32) {
        *reinterpret_cast<uint2*>(&g_qx[((size_t)b * LPAD + (LPAD - 1)) * CIN + c0 + tid * 4]) =
            make_uint2(0u, 0u);
    }

#pragma unroll
    for (int j = 0; j < 16; j++) {
        int ci = j * 8 + warp;
        int row = (ci & 3) * 32 + (ci >> 2);
        float s = fabsf(a_scale[c0 + ci]) + 1e-8f;
        float2 v = *reinterpret_cast<const float2*>(
            &x[((size_t)b * CIN + c0 + ci) * QL + l0 + lane * 2]);
        float q0 = fminf(fmaxf(rintf(v.x / s), -128.f), 127.f);
        float q1 = fminf(fmaxf(rintf(v.y / s), -128.f), 127.f);
        *reinterpret_cast<half2*>(&tile[row][lane * 2]) = __floats2half2_rn(q0, q1);
    }
    __syncthreads();

#pragma unroll
    for (int it = 0; it < 8; it++) {
        int l = it * 8 + warp;
        half2 p0 = __halves2half2(tile[lane +  0][l], tile[lane + 32][l]);
        half2 p1 = __halves2half2(tile[lane + 64][l], tile[lane + 96][l]);
        uint2 w;
        w.x = *reinterpret_cast<uint32_t*>(&p0);
        w.y = *reinterpret_cast<uint32_t*>(&p1);
        *reinterpret_cast<uint2*>(
            &g_qx[((size_t)b * LPAD + l0 + l + 1) * CIN + c0 + lane * 4]) = w;
    }
}

// ---------------- kernel 3: persistent GEMM-conv, warp-phase-rotated ----------------
// R12 structure; each warp starts at tap (wid%3) and ks offset (wid&3) so the 16
// warps' LDSM bursts / MMA phases de-align after each barrier.
__global__ void __launch_bounds__(512, 1)
qconv_gemm(const float* __restrict__ bias, float* __restrict__ out) {
    extern __shared__ __align__(16) char smem[];
    const uint32_t sbase = smem_u32(smem);
    const int tid  = threadIdx.x;
    const int wid  = tid >> 5;
    const int lane = tid & 31;
    const int bid  = blockIdx.x;

    const int wm = (wid & 3) * 32;
    const int wn = (wid >> 2) * 64;
    const int tap0  = wid % 3;       // rotated starting tap
    const int ksoff = wid & 3;       // rotated ks offset

    const uint4* gw = reinterpret_cast<const uint4*>(g_w2);
    const uint4* gx = reinterpret_cast<const uint4*>(g_qx);

    const int ntiles = (NTILES - 1 - bid) / GRID_P + 1;
    const int total  = ntiles * CPT;

    auto load_chunk = [&](int j) {
        const int t  = bid + (j >> 3) * GRID_P;
        const int cc = j & 7;
        const int b  = t >> 6;
        const int o0 = ((t >> 4) & 3) * TILE_M;
        const int L0 = (t & 15) * TILE_N;
        const uint32_t sb = sbase + (uint32_t)(j & 1) * STAGE_BYTES;
#pragma unroll
        for (int k = 0; k < 3; k++)
#pragma unroll
            for (int j2 = 0; j2 < 2; j2++) {
                int e = tid + j2 * 512;
                int r = e >> 3, u = e & 7;
                cp_async16(sb + k * A_TAP_BYTES + (uint32_t)(r * 128) + SWU(u, r),
                           &gw[(size_t)(k * COUT + o0 + r) * 64 + cc * 8 + u]);
            }
#pragma unroll
        for (int j2 = 0; j2 < 5; j2++) {
            int e = tid + j2 * 512;
            if (e < 2064) {
                int r = e >> 3, u = e & 7;
                cp_async16(sb + B_OFF + (uint32_t)(r * 128) + SWU(u, r),
                           &gx[((size_t)b * LPAD + L0 + r) * 64 + cc * 8 + u]);
            }
        }
    };

    float acc[2][8][4];
#pragma unroll
    for (int mi = 0; mi < 2; mi++)
#pragma unroll
        for (int nj = 0; nj < 8; nj++)
#pragma unroll
            for (int q = 0; q < 4; q++) acc[mi][nj][q] = 0.f;

    const int lrow = (lane & 7) + ((lane >> 3) & 1) * 8;
    const int lcol = (lane >> 4);

    auto compute_tap = [&](uint32_t sb, int tap) {
#pragma unroll
        for (int kk = 0; kk < 4; kk++) {
            const int ks = (kk + ksoff) & 3;       // rotated ks order
            const int u = ks * 2 + lcol;
            uint32_t bf[4][4];
#pragma unroll
            for (int t = 0; t < 4; t++) {
                int r = wn + t * 16 + lrow + tap;
                ldm_x4(bf[t][0], bf[t][1], bf[t][2], bf[t][3],
                       sb + B_OFF + r * 128 + SWU(u, r));
            }
            uint32_t af[2][4];
#pragma unroll
            for (int t = 0; t < 2; t++) {
                int r = wm + t * 16 + lrow;
                ldm_x4(af[t][0], af[t][1], af[t][2], af[t][3],
                       sb + tap * A_TAP_BYTES + r * 128 + SWU(u, r));
            }
#pragma unroll
            for (int mi = 0; mi < 2; mi++)
#pragma unroll
                for (int t = 0; t < 4; t++) {
                    mma16816(acc[mi][t*2  ][0], acc[mi][t*2  ][1], acc[mi][t*2  ][2], acc[mi][t*2  ][3],
                             af[mi][0], af[mi][1], af[mi][2], af[mi][3], bf[t][0], bf[t][2]);
                    mma16816(acc[mi][t*2+1][0], acc[mi][t*2+1][1], acc[mi][t*2+1][2], acc[mi][t*2+1][3],
                             af[mi][0], af[mi][1], af[mi][2], af[mi][3], bf[t][1], bf[t][3]);
                }
        }
    };

    load_chunk(0); CP_COMMIT();

    for (int j = 0; j < total; j++) {
        CP_WAIT(0);
        __syncthreads();

        const uint32_t sb = sbase + (uint32_t)(j & 1) * STAGE_BYTES;
        compute_tap(sb, tap0);
        if (j + 1 < total) { load_chunk(j + 1); CP_COMMIT(); }
        compute_tap(sb, tap0 == 2 ? 0 : tap0 + 1);
        compute_tap(sb, tap0 == 0 ? 2 : tap0 - 1);

        if ((j & 7) == 7) {
            const int t  = bid + (j >> 3) * GRID_P;
            const int b  = t >> 6;
            const int o0 = ((t >> 4) & 3) * TILE_M;
            const int L0 = (t & 15) * TILE_N;
#pragma unroll
            for (int mi = 0; mi < 2; mi++) {
                int r0 = wm + mi * 16 + (lane >> 2);
                int o_a = o0 + r0, o_b = o0 + r0 + 8;
                float bv0 = bias[o_a], bv1 = bias[o_b];
                float* pa = out + ((size_t)b * COUT + o_a) * QL + L0;
                float* pb = out + ((size_t)b * COUT + o_b) * QL + L0;
#pragma unroll
                for (int nj = 0; nj < 8; nj++) {
                    int col = wn + nj * 8 + (lane & 3) * 2;
                    float2 v0 = make_float2(acc[mi][nj][0] + bv0, acc[mi][nj][1] + bv0);
                    float2 v1 = make_float2(acc[mi][nj][2] + bv1, acc[mi][nj][3] + bv1);
                    *reinterpret_cast<float2*>(pa + col) = v0;
                    *reinterpret_cast<float2*>(pb + col) = v1;
                }
            }
#pragma unroll
            for (int mi = 0; mi < 2; mi++)
#pragma unroll
                for (int nj = 0; nj < 8; nj++)
#pragma unroll
                    for (int q = 0; q < 4; q++) acc[mi][nj][q] = 0.f;
        }
    }
}

// ---------------- launch ----------------
extern "C" void kernel_launch(void* const* d_in, const int* in_sizes, int n_in,
                              void* d_out, int out_size) {
    (void)in_sizes; (void)n_in; (void)out_size;
    const float* x       = (const float*)d_in[0];
    const float* weight  = (const float*)d_in[1];
    const float* bias    = (const float*)d_in[2];
    const float* a_scale = (const float*)d_in[3];
    const float* w_scale = (const float*)d_in[4];
    float* out = (float*)d_out;

    prep_w_kernel<<<COUT, CIN>>>(weight, a_scale, w_scale);
    quant_kernel<<<dim3(QL / 64, CIN / 128, BATCH), 256>>>(x, a_scale);

    cudaFuncSetAttribute(qconv_gemm, cudaFuncAttributeMaxDynamicSharedMemorySize, SMEM_DYN);
    qconv_gemm<<<GRID_P, 512, SMEM_DYN>>>(bias, out);
}

// round 16
// speedup vs baseline: 1.4568x; 1.0311x over previous
#include <cuda_runtime.h>
#include <cuda_fp16.h>
#include <cstdint>

// ---------------- problem constants ----------------
#define BATCH 32
#define CIN   512
#define COUT  512
#define QL    4096
#define LPAD  4098          // 1 zero row of padding at each end (conv pad=1)

// GEMM tiling: persistent, CTA tile 128(M) x 256(N), 16 warps of 32x64, 1 CTA/SM
#define TILE_M 128
#define TILE_N 256
#define CPT 8               // c-chunks per tile; each chunk covers ALL 3 taps
// stage: A = 3 taps * 128 rows * 128B = 49152 ; B = 258 rows * 128B = 33024
#define A_TAP_BYTES 16384
#define B_OFF 49152
#define STAGE_BYTES 82176
#define SMEM_DYN (2 * STAGE_BYTES)   // 164352 B

#define GRID_P 148
#define NTILES ((QL / TILE_N) * (COUT / TILE_M) * BATCH)   // 2048

// ---------------- device scratch ----------------
__device__ __align__(16) __half g_qx[(size_t)BATCH * LPAD * CIN];   // [b][l+1][c] quantized x (exact ints)
__device__ __align__(16) __half g_w2[(size_t)3 * COUT * CIN];       // [k][o][c]  w'' = qw*sw*sa (fp16)

// ---------------- base-ISA helpers ----------------
__device__ __forceinline__ uint32_t smem_u32(const void* p) {
    uint32_t a;
    asm("{ .reg .u64 t; cvta.to.shared.u64 t, %1; cvt.u32.u64 %0, t; }" : "=r"(a) : "l"(p));
    return a;
}
#define SWU(u, r) (((u) ^ ((r) & 7)) << 4)   // 16B-unit swizzle within a 128B row

__device__ __forceinline__ void cp_async16(uint32_t saddr, const void* gptr) {
    asm volatile("cp.async.cg.shared.global [%0], [%1], 16;" :: "r"(saddr), "l"(gptr));
}
#define CP_COMMIT() asm volatile("cp.async.commit_group;" ::: "memory")
#define CP_WAIT(n)  asm volatile("cp.async.wait_group %0;" :: "n"(n) : "memory")

__device__ __forceinline__ void ldm_x4(uint32_t& r0, uint32_t& r1, uint32_t& r2, uint32_t& r3, uint32_t a) {
    asm volatile("ldmatrix.sync.aligned.m8n8.x4.shared.b16 {%0,%1,%2,%3}, [%4];"
                 : "=r"(r0), "=r"(r1), "=r"(r2), "=r"(r3) : "r"(a));
}
__device__ __forceinline__ void mma16816(float& c0, float& c1, float& c2, float& c3,
                                         uint32_t a0, uint32_t a1, uint32_t a2, uint32_t a3,
                                         uint32_t b0, uint32_t b1) {
    asm("mma.sync.aligned.m16n8k16.row.col.f32.f16.f16.f32 "
        "{%0,%1,%2,%3}, {%4,%5,%6,%7}, {%8,%9}, {%0,%1,%2,%3};"
        : "+f"(c0), "+f"(c1), "+f"(c2), "+f"(c3)
        : "r"(a0), "r"(a1), "r"(a2), "r"(a3), "r"(b0), "r"(b1));
}

// ---------------- kernel 1: fused prep (z==BATCH plane) + quantize/transpose ----------------
// quant: 512 thr, tile 128l x 128c, float4 reads, permuted-row transpose
// (row sigma(ci) = (ci&3)*32 + (ci>>2); 65-word row pitch -> write-phase reads
// stride 65 words between lanes = odd = conflict-free), uint2 coalesced stores.
// prep plane: w'' = clip(rint(w/sw))*sw*sa in fp16, layout [k][o][c].
__global__ void __launch_bounds__(512)
prep_quant_kernel(const float* __restrict__ x, const float* __restrict__ a_scale,
                  const float* __restrict__ w, const float* __restrict__ w_scale) {
    const int tid  = threadIdx.x;

    if (blockIdx.z == BATCH) {
        // ---- weight prep: 128 blocks x 512 thr; each thread: 1 o, 4 c, 3 k ----
        int pid = (blockIdx.y * (QL / 128) + blockIdx.x) * 512 + tid;  // 0..65535
        if (pid < 512 * 128) {
            int o  = pid >> 7;
            int c0 = (pid & 127) * 4;
            float sw = fabsf(w_scale[o]) + 1e-8f;
#pragma unroll
            for (int k = 0; k < 3; k++) {
                __half h[4];
#pragma unroll
                for (int d = 0; d < 4; d++) {
                    float sa = fabsf(a_scale[c0 + d]) + 1e-8f;
                    float v = w[((size_t)o * CIN + c0 + d) * 3 + k];
                    float q = fminf(fmaxf(rintf(v / sw), -128.f), 127.f);
                    h[d] = __float2half_rn((q * sw) * sa);
                }
                *reinterpret_cast<uint2*>(&g_w2[((size_t)k * COUT + o) * CIN + c0]) =
                    *reinterpret_cast<uint2*>(h);
            }
        }
        return;
    }

    __shared__ __half tile[128][130];   // 65-word row pitch (odd)
    const int warp = tid >> 5;          // 0..15
    const int lane = tid & 31;
    const int l0 = blockIdx.x * 128;
    const int c0 = blockIdx.y * 128;
    const int b  = blockIdx.z;

    // fused zero-padding of rows l=-1 and l=QL (c-slice of this block)
    if (blockIdx.x == 0 && tid < 32) {
        *reinterpret_cast<uint2*>(&g_qx[((size_t)b * LPAD + 0) * CIN + c0 + tid * 4]) =
            make_uint2(0u, 0u);
    }
    if (blockIdx.x == (QL / 128) - 1 && tid < 32) {
        *reinterpret_cast<uint2*>(&g_qx[((size_t)b * LPAD + (LPAD - 1)) * CIN + c0 + tid * 4]) =
            make_uint2(0u, 0u);
    }

    // read phase: warp handles channel ci = jj*16+warp, lane reads float4 (4 l)
#pragma unroll
    for (int jj = 0; jj < 8; jj++) {
        int ci = jj * 16 + warp;
        int row = (ci & 3) * 32 + (ci >> 2);
        float s = fabsf(a_scale[c0 + ci]) + 1e-8f;
        float4 v = *reinterpret_cast<const float4*>(
            &x[((size_t)b * CIN + c0 + ci) * QL + l0 + lane * 4]);
        float q0 = fminf(fmaxf(rintf(v.x / s), -128.f), 127.f);
        float q1 = fminf(fmaxf(rintf(v.y / s), -128.f), 127.f);
        float q2 = fminf(fmaxf(rintf(v.z / s), -128.f), 127.f);
        float q3 = fminf(fmaxf(rintf(v.w / s), -128.f), 127.f);
        *reinterpret_cast<half2*>(&tile[row][lane * 4 + 0]) = __floats2half2_rn(q0, q1);
        *reinterpret_cast<half2*>(&tile[row][lane * 4 + 2]) = __floats2half2_rn(q2, q3);
    }
    __syncthreads();

    // write phase: l = it*16+warp; channels 4*lane+k live at rows lane+32k
#pragma unroll
    for (int it = 0; it < 8; it++) {
        int l = it * 16 + warp;
        half2 p0 = __halves2half2(tile[lane +  0][l], tile[lane + 32][l]);
        half2 p1 = __halves2half2(tile[lane + 64][l], tile[lane + 96][l]);
        uint2 wv;
        wv.x = *reinterpret_cast<uint32_t*>(&p0);
        wv.y = *reinterpret_cast<uint32_t*>(&p1);
        *reinterpret_cast<uint2*>(
            &g_qx[((size_t)b * LPAD + l0 + l + 1) * CIN + c0 + lane * 4]) = wv;
    }
}

// ---------------- kernel 2: persistent GEMM-conv (exact R12 winner) ----------------
__global__ void __launch_bounds__(512, 1)
qconv_gemm(const float* __restrict__ bias, float* __restrict__ out) {
    extern __shared__ __align__(16) char smem[];
    const uint32_t sbase = smem_u32(smem);
    const int tid  = threadIdx.x;
    const int wid  = tid >> 5;
    const int lane = tid & 31;
    const int bid  = blockIdx.x;

    const int wm = (wid & 3) * 32;
    const int wn = (wid >> 2) * 64;

    const uint4* gw = reinterpret_cast<const uint4*>(g_w2);
    const uint4* gx = reinterpret_cast<const uint4*>(g_qx);

    const int ntiles = (NTILES - 1 - bid) / GRID_P + 1;
    const int total  = ntiles * CPT;

    auto load_chunk = [&](int j) {
        const int t  = bid + (j >> 3) * GRID_P;
        const int cc = j & 7;
        const int b  = t >> 6;
        const int o0 = ((t >> 4) & 3) * TILE_M;
        const int L0 = (t & 15) * TILE_N;
        const uint32_t sb = sbase + (uint32_t)(j & 1) * STAGE_BYTES;
#pragma unroll
        for (int k = 0; k < 3; k++)
#pragma unroll
            for (int j2 = 0; j2 < 2; j2++) {
                int e = tid + j2 * 512;
                int r = e >> 3, u = e & 7;
                cp_async16(sb + k * A_TAP_BYTES + (uint32_t)(r * 128) + SWU(u, r),
                           &gw[(size_t)(k * COUT + o0 + r) * 64 + cc * 8 + u]);
            }
#pragma unroll
        for (int j2 = 0; j2 < 5; j2++) {
            int e = tid + j2 * 512;
            if (e < 2064) {
                int r = e >> 3, u = e & 7;
                cp_async16(sb + B_OFF + (uint32_t)(r * 128) + SWU(u, r),
                           &gx[((size_t)b * LPAD + L0 + r) * 64 + cc * 8 + u]);
            }
        }
    };

    float acc[2][8][4];
#pragma unroll
    for (int mi = 0; mi < 2; mi++)
#pragma unroll
        for (int nj = 0; nj < 8; nj++)
#pragma unroll
            for (int q = 0; q < 4; q++) acc[mi][nj][q] = 0.f;

    const int lrow = (lane & 7) + ((lane >> 3) & 1) * 8;
    const int lcol = (lane >> 4);

    auto compute_tap = [&](uint32_t sb, int tap) {
#pragma unroll
        for (int ks = 0; ks < 4; ks++) {
            const int u = ks * 2 + lcol;
            uint32_t bf[4][4];
#pragma unroll
            for (int t = 0; t < 4; t++) {
                int r = wn + t * 16 + lrow + tap;
                ldm_x4(bf[t][0], bf[t][1], bf[t][2], bf[t][3],
                       sb + B_OFF + r * 128 + SWU(u, r));
            }
            uint32_t af[2][4];
#pragma unroll
            for (int t = 0; t < 2; t++) {
                int r = wm + t * 16 + lrow;
                ldm_x4(af[t][0], af[t][1], af[t][2], af[t][3],
                       sb + tap * A_TAP_BYTES + r * 128 + SWU(u, r));
            }
#pragma unroll
            for (int mi = 0; mi < 2; mi++)
#pragma unroll
                for (int t = 0; t < 4; t++) {
                    mma16816(acc[mi][t*2  ][0], acc[mi][t*2  ][1], acc[mi][t*2  ][2], acc[mi][t*2  ][3],
                             af[mi][0], af[mi][1], af[mi][2], af[mi][3], bf[t][0], bf[t][2]);
                    mma16816(acc[mi][t*2+1][0], acc[mi][t*2+1][1], acc[mi][t*2+1][2], acc[mi][t*2+1][3],
                             af[mi][0], af[mi][1], af[mi][2], af[mi][3], bf[t][1], bf[t][3]);
                }
        }
    };

    load_chunk(0); CP_COMMIT();

    for (int j = 0; j < total; j++) {
        CP_WAIT(0);
        __syncthreads();

        const uint32_t sb = sbase + (uint32_t)(j & 1) * STAGE_BYTES;
        compute_tap(sb, 0);
        if (j + 1 < total) { load_chunk(j + 1); CP_COMMIT(); }
        compute_tap(sb, 1);
        compute_tap(sb, 2);

        if ((j & 7) == 7) {
            const int t  = bid + (j >> 3) * GRID_P;
            const int b  = t >> 6;
            const int o0 = ((t >> 4) & 3) * TILE_M;
            const int L0 = (t & 15) * TILE_N;
#pragma unroll
            for (int mi = 0; mi < 2; mi++) {
                int r0 = wm + mi * 16 + (lane >> 2);
                int o_a = o0 + r0, o_b = o0 + r0 + 8;
                float bv0 = bias[o_a], bv1 = bias[o_b];
                float* pa = out + ((size_t)b * COUT + o_a) * QL + L0;
                float* pb = out + ((size_t)b * COUT + o_b) * QL + L0;
#pragma unroll
                for (int nj = 0; nj < 8; nj++) {
                    int col = wn + nj * 8 + (lane & 3) * 2;
                    float2 v0 = make_float2(acc[mi][nj][0] + bv0, acc[mi][nj][1] + bv0);
                    float2 v1 = make_float2(acc[mi][nj][2] + bv1, acc[mi][nj][3] + bv1);
                    *reinterpret_cast<float2*>(pa + col) = v0;
                    *reinterpret_cast<float2*>(pb + col) = v1;
                }
            }
#pragma unroll
            for (int mi = 0; mi < 2; mi++)
#pragma unroll
                for (int nj = 0; nj < 8; nj++)
#pragma unroll
                    for (int q = 0; q < 4; q++) acc[mi][nj][q] = 0.f;
        }
    }
}

// ---------------- launch ----------------
extern "C" void kernel_launch(void* const* d_in, const int* in_sizes, int n_in,
                              void* d_out, int out_size) {
    (void)in_sizes; (void)n_in; (void)out_size;
    const float* x       = (const float*)d_in[0];
    const float* weight  = (const float*)d_in[1];
    const float* bias    = (const float*)d_in[2];
    const float* a_scale = (const float*)d_in[3];
    const float* w_scale = (const float*)d_in[4];
    float* out = (float*)d_out;

    // z planes 0..BATCH-1: quantize+transpose; plane BATCH: weight prep
    prep_quant_kernel<<<dim3(QL / 128, CIN / 128, BATCH + 1), 512>>>(x, a_scale, weight, w_scale);

    cudaFuncSetAttribute(qconv_gemm, cudaFuncAttributeMaxDynamicSharedMemorySize, SMEM_DYN);
    qconv_gemm<<<GRID_P, 512, SMEM_DYN>>>(bias, out);
}

// round 17
// speedup vs baseline: 1.4643x; 1.0051x over previous
#include <cuda_runtime.h>
#include <cuda_fp16.h>
#include <cstdint>

// ---------------- problem constants ----------------
#define BATCH 32
#define CIN   512
#define COUT  512
#define QL    4096
#define LPAD  4098          // 1 zero row of padding at each end (conv pad=1)

// GEMM tiling: persistent, CTA tile 128(M) x 256(N), 16 warps of 32x64, 1 CTA/SM
#define TILE_M 128
#define TILE_N 256
#define CPT 8               // c-chunks per tile; each chunk covers ALL 3 taps
// stage: A = 3 taps * 128 rows * 128B = 49152 ; B = 258 rows * 128B = 33024
#define A_TAP_BYTES 16384
#define B_OFF 49152
#define STAGE_BYTES 82176
#define SMEM_DYN (2 * STAGE_BYTES)   // 164352 B

#define GRID_P 148
#define NTILES ((QL / TILE_N) * (COUT / TILE_M) * BATCH)   // 2048

// ---------------- device scratch ----------------
__device__ __align__(16) __half g_qx[(size_t)BATCH * LPAD * CIN];   // [b][l+1][c] quantized x (exact ints)
__device__ __align__(16) __half g_w2[(size_t)3 * COUT * CIN];       // [k][o][c]  w'' = qw*sw*sa (fp16)

// ---------------- base-ISA helpers ----------------
__device__ __forceinline__ uint32_t smem_u32(const void* p) {
    uint32_t a;
    asm("{ .reg .u64 t; cvta.to.shared.u64 t, %1; cvt.u32.u64 %0, t; }" : "=r"(a) : "l"(p));
    return a;
}
#define SWU(u, r) (((u) ^ ((r) & 7)) << 4)   // 16B-unit swizzle within a 128B row

__device__ __forceinline__ void cp_async16(uint32_t saddr, const void* gptr) {
    asm volatile("cp.async.cg.shared.global [%0], [%1], 16;" :: "r"(saddr), "l"(gptr));
}
#define CP_COMMIT() asm volatile("cp.async.commit_group;" ::: "memory")
#define CP_WAIT(n)  asm volatile("cp.async.wait_group %0;" :: "n"(n) : "memory")

__device__ __forceinline__ void ldm_x4(uint32_t& r0, uint32_t& r1, uint32_t& r2, uint32_t& r3, uint32_t a) {
    asm volatile("ldmatrix.sync.aligned.m8n8.x4.shared.b16 {%0,%1,%2,%3}, [%4];"
                 : "=r"(r0), "=r"(r1), "=r"(r2), "=r"(r3) : "r"(a));
}
__device__ __forceinline__ void mma16816(float& c0, float& c1, float& c2, float& c3,
                                         uint32_t a0, uint32_t a1, uint32_t a2, uint32_t a3,
                                         uint32_t b0, uint32_t b1) {
    asm("mma.sync.aligned.m16n8k16.row.col.f32.f16.f16.f32 "
        "{%0,%1,%2,%3}, {%4,%5,%6,%7}, {%8,%9}, {%0,%1,%2,%3};"
        : "+f"(c0), "+f"(c1), "+f"(c2), "+f"(c3)
        : "r"(a0), "r"(a1), "r"(a2), "r"(a3), "r"(b0), "r"(b1));
}

// ---------------- kernel 1: fused prep (z==BATCH plane) + quantize/transpose ----------------
// quant: 512 thr, tile 128l x 128c, float4 reads. Permutation
// sigma(ci) = (ci&7)*16 + (ci>>3): lane L'=lane&15 owns 8 CONTIGUOUS channels
// (ci = 8L'+k lives at row 16k+L'), so the write phase packs one uint4 (16B)
// per lane and each half-warp covers a full 256B segment. Row pitch 65 words
// (odd) -> write-phase column reads are conflict-free (lane stride 65 banks;
// the two l lane-groups hit the same word -> broadcast).
__global__ void __launch_bounds__(512)
prep_quant_kernel(const float* __restrict__ x, const float* __restrict__ a_scale,
                  const float* __restrict__ w, const float* __restrict__ w_scale) {
    const int tid  = threadIdx.x;

    if (blockIdx.z == BATCH) {
        // ---- weight prep: each thread: 1 o, 4 c, 3 k ----
        int pid = (blockIdx.y * (QL / 128) + blockIdx.x) * 512 + tid;  // 0..65535
        if (pid < 512 * 128) {
            int o  = pid >> 7;
            int c0 = (pid & 127) * 4;
            float sw = fabsf(w_scale[o]) + 1e-8f;
#pragma unroll
            for (int k = 0; k < 3; k++) {
                __half h[4];
#pragma unroll
                for (int d = 0; d < 4; d++) {
                    float sa = fabsf(a_scale[c0 + d]) + 1e-8f;
                    float v = w[((size_t)o * CIN + c0 + d) * 3 + k];
                    float q = fminf(fmaxf(rintf(v / sw), -128.f), 127.f);
                    h[d] = __float2half_rn((q * sw) * sa);
                }
                *reinterpret_cast<uint2*>(&g_w2[((size_t)k * COUT + o) * CIN + c0]) =
                    *reinterpret_cast<uint2*>(h);
            }
        }
        return;
    }

    __shared__ __half tile[128][130];   // 65-word row pitch (odd)
    const int warp = tid >> 5;          // 0..15
    const int lane = tid & 31;
    const int l0 = blockIdx.x * 128;
    const int c0 = blockIdx.y * 128;
    const int b  = blockIdx.z;

    // fused zero-padding of rows l=-1 and l=QL (c-slice of this block)
    if (blockIdx.x == 0 && tid < 16) {
        *reinterpret_cast<uint4*>(&g_qx[((size_t)b * LPAD + 0) * CIN + c0 + tid * 8]) =
            make_uint4(0u, 0u, 0u, 0u);
    }
    if (blockIdx.x == (QL / 128) - 1 && tid < 16) {
        *reinterpret_cast<uint4*>(&g_qx[((size_t)b * LPAD + (LPAD - 1)) * CIN + c0 + tid * 8]) =
            make_uint4(0u, 0u, 0u, 0u);
    }

    // read phase: warp handles channel ci = jj*16+warp, lane reads float4 (4 l)
#pragma unroll
    for (int jj = 0; jj < 8; jj++) {
        int ci = jj * 16 + warp;
        int row = (ci & 7) * 16 + (ci >> 3);
        float s = fabsf(a_scale[c0 + ci]) + 1e-8f;
        float4 v = *reinterpret_cast<const float4*>(
            &x[((size_t)b * CIN + c0 + ci) * QL + l0 + lane * 4]);
        float q0 = fminf(fmaxf(rintf(v.x / s), -128.f), 127.f);
        float q1 = fminf(fmaxf(rintf(v.y / s), -128.f), 127.f);
        float q2 = fminf(fmaxf(rintf(v.z / s), -128.f), 127.f);
        float q3 = fminf(fmaxf(rintf(v.w / s), -128.f), 127.f);
        *reinterpret_cast<half2*>(&tile[row][lane * 4 + 0]) = __floats2half2_rn(q0, q1);
        *reinterpret_cast<half2*>(&tile[row][lane * 4 + 2]) = __floats2half2_rn(q2, q3);
    }
    __syncthreads();

    // write phase: lane L'=lane&15 packs channels 8L'..8L'+7 (rows 16k+L') for
    // l = it*32 + warp*2 + (lane>>4); one uint4 store per lane per iteration.
#pragma unroll
    for (int it = 0; it < 4; it++) {
        int l  = it * 32 + warp * 2 + (lane >> 4);
        int Lp = lane & 15;
        __half h[8];
#pragma unroll
        for (int k = 0; k < 8; k++) h[k] = tile[k * 16 + Lp][l];
        *reinterpret_cast<uint4*>(
            &g_qx[((size_t)b * LPAD + l0 + l + 1) * CIN + c0 + Lp * 8]) =
            *reinterpret_cast<uint4*>(h);
    }
}

// ---------------- kernel 2: persistent GEMM-conv (exact R12/R16 winner) ----------------
__global__ void __launch_bounds__(512, 1)
qconv_gemm(const float* __restrict__ bias, float* __restrict__ out) {
    extern __shared__ __align__(16) char smem[];
    const uint32_t sbase = smem_u32(smem);
    const int tid  = threadIdx.x;
    const int wid  = tid >> 5;
    const int lane = tid & 31;
    const int bid  = blockIdx.x;

    const int wm = (wid & 3) * 32;
    const int wn = (wid >> 2) * 64;

    const uint4* gw = reinterpret_cast<const uint4*>(g_w2);
    const uint4* gx = reinterpret_cast<const uint4*>(g_qx);

    const int ntiles = (NTILES - 1 - bid) / GRID_P + 1;
    const int total  = ntiles * CPT;

    auto load_chunk = [&](int j) {
        const int t  = bid + (j >> 3) * GRID_P;
        const int cc = j & 7;
        const int b  = t >> 6;
        const int o0 = ((t >> 4) & 3) * TILE_M;
        const int L0 = (t & 15) * TILE_N;
        const uint32_t sb = sbase + (uint32_t)(j & 1) * STAGE_BYTES;
#pragma unroll
        for (int k = 0; k < 3; k++)
#pragma unroll
            for (int j2 = 0; j2 < 2; j2++) {
                int e = tid + j2 * 512;
                int r = e >> 3, u = e & 7;
                cp_async16(sb + k * A_TAP_BYTES + (uint32_t)(r * 128) + SWU(u, r),
                           &gw[(size_t)(k * COUT + o0 + r) * 64 + cc * 8 + u]);
            }
#pragma unroll
        for (int j2 = 0; j2 < 5; j2++) {
            int e = tid + j2 * 512;
            if (e < 2064) {
                int r = e >> 3, u = e & 7;
                cp_async16(sb + B_OFF + (uint32_t)(r * 128) + SWU(u, r),
                           &gx[((size_t)b * LPAD + L0 + r) * 64 + cc * 8 + u]);
            }
        }
    };

    float acc[2][8][4];
#pragma unroll
    for (int mi = 0; mi < 2; mi++)
#pragma unroll
        for (int nj = 0; nj < 8; nj++)
#pragma unroll
            for (int q = 0; q < 4; q++) acc[mi][nj][q] = 0.f;

    const int lrow = (lane & 7) + ((lane >> 3) & 1) * 8;
    const int lcol = (lane >> 4);

    auto compute_tap = [&](uint32_t sb, int tap) {
#pragma unroll
        for (int ks = 0; ks < 4; ks++) {
            const int u = ks * 2 + lcol;
            uint32_t bf[4][4];
#pragma unroll
            for (int t = 0; t < 4; t++) {
                int r = wn + t * 16 + lrow + tap;
                ldm_x4(bf[t][0], bf[t][1], bf[t][2], bf[t][3],
                       sb + B_OFF + r * 128 + SWU(u, r));
            }
            uint32_t af[2][4];
#pragma unroll
            for (int t = 0; t < 2; t++) {
                int r = wm + t * 16 + lrow;
                ldm_x4(af[t][0], af[t][1], af[t][2], af[t][3],
                       sb + tap * A_TAP_BYTES + r * 128 + SWU(u, r));
            }
#pragma unroll
            for (int mi = 0; mi < 2; mi++)
#pragma unroll
                for (int t = 0; t < 4; t++) {
                    mma16816(acc[mi][t*2  ][0], acc[mi][t*2  ][1], acc[mi][t*2  ][2], acc[mi][t*2  ][3],
                             af[mi][0], af[mi][1], af[mi][2], af[mi][3], bf[t][0], bf[t][2]);
                    mma16816(acc[mi][t*2+1][0], acc[mi][t*2+1][1], acc[mi][t*2+1][2], acc[mi][t*2+1][3],
                             af[mi][0], af[mi][1], af[mi][2], af[mi][3], bf[t][1], bf[t][3]);
                }
        }
    };

    load_chunk(0); CP_COMMIT();

    for (int j = 0; j < total; j++) {
        CP_WAIT(0);
        __syncthreads();

        const uint32_t sb = sbase + (uint32_t)(j & 1) * STAGE_BYTES;
        compute_tap(sb, 0);
        if (j + 1 < total) { load_chunk(j + 1); CP_COMMIT(); }
        compute_tap(sb, 1);
        compute_tap(sb, 2);

        if ((j & 7) == 7) {
            const int t  = bid + (j >> 3) * GRID_P;
            const int b  = t >> 6;
            const int o0 = ((t >> 4) & 3) * TILE_M;
            const int L0 = (t & 15) * TILE_N;
#pragma unroll
            for (int mi = 0; mi < 2; mi++) {
                int r0 = wm + mi * 16 + (lane >> 2);
                int o_a = o0 + r0, o_b = o0 + r0 + 8;
                float bv0 = bias[o_a], bv1 = bias[o_b];
                float* pa = out + ((size_t)b * COUT + o_a) * QL + L0;
                float* pb = out + ((size_t)b * COUT + o_b) * QL + L0;
#pragma unroll
                for (int nj = 0; nj < 8; nj++) {
                    int col = wn + nj * 8 + (lane & 3) * 2;
                    float2 v0 = make_float2(acc[mi][nj][0] + bv0, acc[mi][nj][1] + bv0);
                    float2 v1 = make_float2(acc[mi][nj][2] + bv1, acc[mi][nj][3] + bv1);
                    *reinterpret_cast<float2*>(pa + col) = v0;
                    *reinterpret_cast<float2*>(pb + col) = v1;
                }
            }
#pragma unroll
            for (int mi = 0; mi < 2; mi++)
#pragma unroll
                for (int nj = 0; nj < 8; nj++)
#pragma unroll
                    for (int q = 0; q < 4; q++) acc[mi][nj][q] = 0.f;
        }
    }
}

// ---------------- launch ----------------
extern "C" void kernel_launch(void* const* d_in, const int* in_sizes, int n_in,
                              void* d_out, int out_size) {
    (void)in_sizes; (void)n_in; (void)out_size;
    const float* x       = (const float*)d_in[0];
    const float* weight  = (const float*)d_in[1];
    const float* bias    = (const float*)d_in[2];
    const float* a_scale = (const float*)d_in[3];
    const float* w_scale = (const float*)d_in[4];
    float* out = (float*)d_out;

    // z planes 0..BATCH-1: quantize+transpose; plane BATCH: weight prep
    prep_quant_kernel<<<dim3(QL / 128, CIN / 128, BATCH + 1), 512>>>(x, a_scale, weight, w_scale);

    cudaFuncSetAttribute(qconv_gemm, cudaFuncAttributeMaxDynamicSharedMemorySize, SMEM_DYN);
    qconv_gemm<<<GRID_P, 512, SMEM_DYN>>>(bias, out);
}